// round 13
// baseline (speedup 1.0000x reference)
#include <cuda_runtime.h>
#include <cuda_fp16.h>
#include <math.h>
#include <stdint.h>

#define BB 4
#define TT 2048
#define HH 1024
#define NH 16
#define HD 64
#define H3 3072

// Scratch (allocation-free rule: __device__ globals)
__device__ __half g_qkv[(size_t)BB * TT * H3];  // (B,T,3H) fp16
__device__ __half g_att[(size_t)BB * TT * HH];  // (B,T,H)  fp16
__device__ __half g_xr [(size_t)BB * TT * HH];  // input fp16
__device__ __half g_wqT[(size_t)H3 * HH];       // w_qkv^T (3H,H) fp16
__device__ __half g_woT[(size_t)HH * HH];       // w_out^T (H,H) fp16
__device__ int    g_len[BB];

// ---------------------------------------------------------------------------
// helpers
// ---------------------------------------------------------------------------
__device__ __forceinline__ void mma_f16(
    float* d, const unsigned* a, const unsigned* b)
{
    asm volatile(
        "mma.sync.aligned.m16n8k16.row.col.f32.f16.f16.f32 "
        "{%0,%1,%2,%3}, {%4,%5,%6,%7}, {%8,%9}, {%0,%1,%2,%3};\n"
        : "+f"(d[0]), "+f"(d[1]), "+f"(d[2]), "+f"(d[3])
        : "r"(a[0]), "r"(a[1]), "r"(a[2]), "r"(a[3]),
          "r"(b[0]), "r"(b[1]));
}

__device__ __forceinline__ uint32_t smem_u32(const void* p) {
    uint32_t a;
    asm("{ .reg .u64 t; cvta.to.shared.u64 t, %1; cvt.u32.u64 %0, t; }"
        : "=r"(a) : "l"(p));
    return a;
}

__device__ __forceinline__ unsigned packh2(float a, float b) {
    __half2 h = __floats2half2_rn(a, b);
    return *(unsigned*)&h;
}

#define CP16(dst, src) \
    asm volatile("cp.async.ca.shared.global [%0], [%1], 16;" \
                 :: "r"(dst), "l"(src) : "memory")
#define CPCOMMIT() asm volatile("cp.async.commit_group;" ::: "memory")

#define LDSM4(r0, r1, r2, r3, addr) \
    asm volatile("ldmatrix.sync.aligned.m8n8.x4.shared.b16 {%0,%1,%2,%3}, [%4];" \
                 : "=r"(r0), "=r"(r1), "=r"(r2), "=r"(r3) : "r"(addr))

#define LDSM4T(r0, r1, r2, r3, addr) \
    asm volatile("ldmatrix.sync.aligned.m8n8.x4.trans.shared.b16 {%0,%1,%2,%3}, [%4];" \
                 : "=r"(r0), "=r"(r1), "=r"(r2), "=r"(r3) : "r"(addr))

// SW128 swizzle on 16B granules within a 128B row
#define SWR(row, byteoff) (((row) * 128 + (byteoff)) ^ (((row) & 7) << 4))

// ---------------------------------------------------------------------------
// Fused prepass: len + input cvt + both weight transposes, one launch.
// ---------------------------------------------------------------------------
#define PREP_CVT0   4
#define PREP_CVTN   2048
#define PREP_TQ0    (PREP_CVT0 + PREP_CVTN)          // 2052
#define PREP_TQN    ((H3 / 32) * (HH / 32))          // 3072
#define PREP_TO0    (PREP_TQ0 + PREP_TQN)            // 5124
#define PREP_TON    ((HH / 32) * (HH / 32))          // 1024
#define PREP_BLOCKS (PREP_TO0 + PREP_TON)            // 6148

__global__ void prep_kernel(
    const unsigned char* __restrict__ mask, const float* __restrict__ inp,
    const float* __restrict__ w_qkv, const float* __restrict__ w_out,
    __half* __restrict__ xr, __half* __restrict__ wqT, __half* __restrict__ woT)
{
    __shared__ float sf[32][33];
    const int bid = blockIdx.x;
    const int tid = threadIdx.x;

    if (bid < 4) {
        __shared__ int sred[256];
        const unsigned int w0 = *(const unsigned int*)mask;
        const int b = bid;
        int cnt = 0;
        if (w0 == 0x01010101u) {
            for (int t = tid; t < TT; t += 256)
                cnt += (mask[(size_t)b * TT + t] != 0) ? 1 : 0;
        } else if (w0 == 0x3F800000u) {
            const float* m = (const float*)mask;
            for (int t = tid; t < TT; t += 256)
                cnt += (m[(size_t)b * TT + t] != 0.f) ? 1 : 0;
        } else {
            const int* m = (const int*)mask;
            for (int t = tid; t < TT; t += 256)
                cnt += (m[(size_t)b * TT + t] != 0) ? 1 : 0;
        }
        sred[tid] = cnt;
        __syncthreads();
        for (int s = 128; s > 0; s >>= 1) {
            if (tid < s) sred[tid] += sred[tid + s];
            __syncthreads();
        }
        if (tid == 0) g_len[b] = sred[0];
    } else if (bid < PREP_TQ0) {
        const float4* in = (const float4*)inp;
        uint2* out = (uint2*)xr;
        const int n4 = (BB * TT * HH) / 4;
        for (int i = (bid - PREP_CVT0) * 256 + tid; i < n4;
             i += PREP_CVTN * 256) {
            float4 v = in[i];
            out[i] = make_uint2(packh2(v.x, v.y), packh2(v.z, v.w));
        }
    } else {
        const float* S;
        __half* D;
        int R, C, tb;
        if (bid < PREP_TO0) {
            S = w_qkv; D = wqT; R = HH; C = H3; tb = bid - PREP_TQ0;
        } else {
            S = w_out; D = woT; R = HH; C = HH; tb = bid - PREP_TO0;
        }
        const int nbx = C / 32;
        const int bx = tb % nbx;
        const int by = tb / nbx;
        const int tx = tid & 31;
        const int ty = tid >> 5;
        const int x = bx * 32 + tx;
        const int y0 = by * 32;
        #pragma unroll
        for (int i = ty; i < 32; i += 8)
            sf[i][tx] = S[(size_t)(y0 + i) * C + x];
        __syncthreads();
        const int xo = y0 + tx;
        const int yo0 = bx * 32;
        #pragma unroll
        for (int i = ty; i < 32; i += 8)
            D[(size_t)(yo0 + i) * R + xo] = __float2half_rn(sf[tx][i]);
    }
}

// ---------------------------------------------------------------------------
// fp16 HMMA GEMM: CTA 128x128, FOUR warps of 64x64 (2x2), K-chunk 64 halves,
// 3-stage cp.async pipeline, ONE sync per K-chunk, m16n8k16.
// Halves LDSM re-read amplification vs 8x(64x32): A 2x (was 4x), B 2x.
// Smem: 3 x (A 16KB + B 16KB) = 96KB -> 2 CTAs/SM (8 warps/SM preserved).
// ---------------------------------------------------------------------------
#define TG_AST  16384
#define TG_SMEM (6 * TG_AST)

template <bool HOUT>
__global__ __launch_bounds__(128) void hgemm(
    const __half* __restrict__ A, const __half* __restrict__ Bt,
    const float* __restrict__ bias, void* __restrict__ Cv,
    int M, int N, int K)
{
    extern __shared__ char smem[];
    const uint32_t base = smem_u32(smem);

    const int tid   = threadIdx.x;
    const int warp  = tid >> 5;
    const int lane  = tid & 31;
    const int g     = lane >> 2;
    const int t     = lane & 3;
    const int warpM = warp & 1;        // 2 x 64 rows
    const int warpN = warp >> 1;       // 2 x 64 cols
    const int brow  = blockIdx.y * 128;
    const int bcol  = blockIdx.x * 128;

    uint32_t sA[3], sB[3];
    #pragma unroll
    for (int s = 0; s < 3; s++) {
        sA[s] = base + s * TG_AST;
        sB[s] = base + 3 * TG_AST + s * TG_AST;
    }

    // loader: each thread owns one 128B row of A and of B per chunk
    const __half* Ap = A  + (size_t)(brow + tid) * K;
    const __half* Bp = Bt + (size_t)(bcol + tid) * K;
    uint32_t swl[8];
    #pragma unroll
    for (int q = 0; q < 8; q++) swl[q] = SWR(tid, q * 16);

    // consumer lane maps (R11-proven)
    const int arow16 = lane & 15;
    const int acol16 = (lane >> 4) * 16;
    const int brow_i = (lane & 7) + (lane >> 4) * 8;
    const int bcol_i = ((lane >> 3) & 1) * 16;

    float acc[4][8][4];
    #pragma unroll
    for (int i = 0; i < 4; i++)
        #pragma unroll
        for (int j = 0; j < 8; j++)
            #pragma unroll
            for (int q = 0; q < 4; q++) acc[i][j][q] = 0.f;

    const int nch = K >> 6;   // 64-half chunks

    // prologue: chunks 0,1 -> stages 0,1
    #pragma unroll
    for (int pc = 0; pc < 2; pc++) {
        #pragma unroll
        for (int q = 0; q < 8; q++) {
            CP16(sA[pc] + swl[q], Ap + pc * 64 + q * 8);
            CP16(sB[pc] + swl[q], Bp + pc * 64 + q * 8);
        }
        CPCOMMIT();
    }

    int st = 0, sp = 2;
    for (int kc = 0; kc < nch; kc++) {
        if (kc < nch - 1)
            asm volatile("cp.async.wait_group 1;" ::: "memory");
        else
            asm volatile("cp.async.wait_group 0;" ::: "memory");
        __syncthreads();

        if (kc + 2 < nch) {
            const __half* Ap2 = Ap + (kc + 2) * 64;
            const __half* Bp2 = Bp + (kc + 2) * 64;
            #pragma unroll
            for (int q = 0; q < 8; q++) {
                CP16(sA[sp] + swl[q], Ap2 + q * 8);
                CP16(sB[sp] + swl[q], Bp2 + q * 8);
            }
            CPCOMMIT();
        }

        const uint32_t aBase = sA[st];
        const uint32_t bBase = sB[st];

        #pragma unroll
        for (int ks = 0; ks < 4; ks++) {
            const int kb = ks * 32;   // k16 sub-chunk = 32 bytes
            unsigned af[4][4];
            #pragma unroll
            for (int mt = 0; mt < 4; mt++) {
                const int r = warpM * 64 + mt * 16 + arow16;
                LDSM4(af[mt][0], af[mt][1], af[mt][2], af[mt][3],
                      aBase + SWR(r, kb + acol16));
            }
            unsigned bf[8][2];
            #pragma unroll
            for (int np = 0; np < 4; np++) {
                const int r = warpN * 64 + np * 16 + brow_i;
                unsigned r0, r1, r2, r3;
                LDSM4(r0, r1, r2, r3, bBase + SWR(r, kb + bcol_i));
                bf[np * 2][0] = r0;      bf[np * 2][1] = r1;
                bf[np * 2 + 1][0] = r2;  bf[np * 2 + 1][1] = r3;
            }
            #pragma unroll
            for (int mt = 0; mt < 4; mt++)
                #pragma unroll
                for (int nt = 0; nt < 8; nt++)
                    mma_f16(acc[mt][nt], af[mt], bf[nt]);
        }

        st = (st == 2) ? 0 : st + 1;
        sp = (sp == 2) ? 0 : sp + 1;
    }

    // epilogue: bias + store (warp writes its 64x64)
    #pragma unroll
    for (int mt = 0; mt < 4; mt++) {
        const int r0 = brow + warpM * 64 + mt * 16 + g;
        #pragma unroll
        for (int nt = 0; nt < 8; nt++) {
            const int c = bcol + warpN * 64 + nt * 8 + 2 * t;
            const float bv0 = bias[c], bv1 = bias[c + 1];
            if (HOUT) {
                __half* C = (__half*)Cv;
                *(unsigned*)&C[(size_t)r0 * N + c] =
                    packh2(acc[mt][nt][0] + bv0, acc[mt][nt][1] + bv1);
                *(unsigned*)&C[(size_t)(r0 + 8) * N + c] =
                    packh2(acc[mt][nt][2] + bv0, acc[mt][nt][3] + bv1);
            } else {
                float* C = (float*)Cv;
                float2 v0 = {acc[mt][nt][0] + bv0, acc[mt][nt][1] + bv1};
                float2 v1 = {acc[mt][nt][2] + bv0, acc[mt][nt][3] + bv1};
                *(float2*)&C[(size_t)r0 * N + c]       = v0;
                *(float2*)&C[(size_t)(r0 + 8) * N + c] = v1;
            }
        }
    }
}

// ---------------------------------------------------------------------------
// FA2 fp16 attention (R11-proven, unchanged)
// ---------------------------------------------------------------------------
#define AT_SMEM 49152

__global__ __launch_bounds__(256) void attn_h(
    const __half* __restrict__ qkv, __half* __restrict__ att)
{
    extern __shared__ char sm[];
    const uint32_t smb = smem_u32(sm);

    const int tid  = threadIdx.x;
    const int warp = tid >> 5;
    const int lane = tid & 31;
    const int g = lane >> 2;
    const int t = lane & 3;
    const int qt = blockIdx.x;
    const int b  = blockIdx.y >> 4;
    const int h  = blockIdx.y & 15;
    const int len = g_len[b];

    const __half* qb = qkv + (size_t)b * TT * H3 + h * HD;
    const __half* kb = qb + HH;
    const __half* vb = qb + 2 * HH;

    {
        const int r = tid >> 1;
        #pragma unroll
        for (int q = 0; q < 4; q++) {
            const int gq = (tid & 1) * 4 + q;
            uint4 v = *(const uint4*)(qb + (size_t)(qt * 128 + r) * H3 + gq * 8);
            *(uint4*)(sm + SWR(r, gq * 16)) = v;
        }
    }
    __syncthreads();

    const int arow16 = lane & 15;
    const int acol16 = (lane >> 4) * 16;
    const int brow_i = (lane & 7) + (lane >> 4) * 8;
    const int bcol_i = ((lane >> 3) & 1) * 16;

    unsigned qf[4][4];
    #pragma unroll
    for (int ks = 0; ks < 4; ks++)
        LDSM4(qf[ks][0], qf[ks][1], qf[ks][2], qf[ks][3],
              smb + SWR(warp * 16 + arow16, ks * 32 + acol16));
    __syncthreads();

    float m0 = -1e30f, m1 = -1e30f, l0 = 0.f, l1 = 0.f;
    float o[8][4];
    #pragma unroll
    for (int nt = 0; nt < 8; nt++)
        #pragma unroll
        for (int q = 0; q < 4; q++) o[nt][q] = 0.f;

    const int row0 = qt * 128 + warp * 16 + g;
    const int kt_max = min(2 * qt + 1, (len - 1) >> 6);

    const int rv  = tid >> 2;
    const int gk0 = (tid & 3) * 2;

    uint4 kreg[2], vreg[2];
    #pragma unroll
    for (int j = 0; j < 2; j++) {
        kreg[j] = *(const uint4*)(kb + (size_t)rv * H3 + (gk0 + j) * 8);
        vreg[j] = *(const uint4*)(vb + (size_t)rv * H3 + (gk0 + j) * 8);
    }

    for (int kt = 0; kt <= kt_max; kt++) {
        const int buf = kt & 1;
        const uint32_t kbuf = smb + buf * 8192;
        const uint32_t vbuf = smb + 16384 + buf * 8192;

        #pragma unroll
        for (int j = 0; j < 2; j++) {
            *(uint4*)(sm + buf * 8192 + SWR(rv, (gk0 + j) * 16)) = kreg[j];
            *(uint4*)(sm + 16384 + buf * 8192 + SWR(rv, (gk0 + j) * 16)) = vreg[j];
        }
        __syncthreads();

        if (kt < kt_max) {
            #pragma unroll
            for (int j = 0; j < 2; j++) {
                const size_t ro = (size_t)((kt + 1) * 64 + rv) * H3 + (gk0 + j) * 8;
                kreg[j] = *(const uint4*)(kb + ro);
                vreg[j] = *(const uint4*)(vb + ro);
            }
        }

        float s[8][4];
        #pragma unroll
        for (int nt = 0; nt < 8; nt++)
            #pragma unroll
            for (int q = 0; q < 4; q++) s[nt][q] = 0.f;

        #pragma unroll
        for (int ks = 0; ks < 4; ks++) {
            unsigned bf[8][2];
            #pragma unroll
            for (int np = 0; np < 4; np++) {
                unsigned r0, r1, r2, r3;
                LDSM4(r0, r1, r2, r3,
                      kbuf + SWR(np * 16 + brow_i, ks * 32 + bcol_i));
                bf[np * 2][0] = r0;      bf[np * 2][1] = r1;
                bf[np * 2 + 1][0] = r2;  bf[np * 2 + 1][1] = r3;
            }
            #pragma unroll
            for (int nt = 0; nt < 8; nt++)
                mma_f16(s[nt], qf[ks], bf[nt]);
        }

        #pragma unroll
        for (int nt = 0; nt < 8; nt++) {
            const int c0 = kt * 64 + nt * 8 + 2 * t;
            s[nt][0] = (c0     <= row0     && c0     < len) ? s[nt][0] * 0.125f : -1e30f;
            s[nt][1] = (c0 + 1 <= row0     && c0 + 1 < len) ? s[nt][1] * 0.125f : -1e30f;
            s[nt][2] = (c0     <= row0 + 8 && c0     < len) ? s[nt][2] * 0.125f : -1e30f;
            s[nt][3] = (c0 + 1 <= row0 + 8 && c0 + 1 < len) ? s[nt][3] * 0.125f : -1e30f;
        }

        float mx0 = -1e30f, mx1 = -1e30f;
        #pragma unroll
        for (int nt = 0; nt < 8; nt++) {
            mx0 = fmaxf(mx0, fmaxf(s[nt][0], s[nt][1]));
            mx1 = fmaxf(mx1, fmaxf(s[nt][2], s[nt][3]));
        }
        mx0 = fmaxf(mx0, __shfl_xor_sync(0xffffffffu, mx0, 1));
        mx0 = fmaxf(mx0, __shfl_xor_sync(0xffffffffu, mx0, 2));
        mx1 = fmaxf(mx1, __shfl_xor_sync(0xffffffffu, mx1, 1));
        mx1 = fmaxf(mx1, __shfl_xor_sync(0xffffffffu, mx1, 2));

        const float mn0 = fmaxf(m0, mx0);
        const float mn1 = fmaxf(m1, mx1);
        const float a0 = __expf(m0 - mn0);
        const float a1 = __expf(m1 - mn1);
        m0 = mn0; m1 = mn1;

        float sum0 = 0.f, sum1 = 0.f;
        #pragma unroll
        for (int nt = 0; nt < 8; nt++) {
            s[nt][0] = __expf(s[nt][0] - mn0);
            s[nt][1] = __expf(s[nt][1] - mn0);
            s[nt][2] = __expf(s[nt][2] - mn1);
            s[nt][3] = __expf(s[nt][3] - mn1);
            sum0 += s[nt][0] + s[nt][1];
            sum1 += s[nt][2] + s[nt][3];
        }
        sum0 += __shfl_xor_sync(0xffffffffu, sum0, 1);
        sum0 += __shfl_xor_sync(0xffffffffu, sum0, 2);
        sum1 += __shfl_xor_sync(0xffffffffu, sum1, 1);
        sum1 += __shfl_xor_sync(0xffffffffu, sum1, 2);
        l0 = l0 * a0 + sum0;
        l1 = l1 * a1 + sum1;

        #pragma unroll
        for (int nt = 0; nt < 8; nt++) {
            o[nt][0] *= a0; o[nt][1] *= a0;
            o[nt][2] *= a1; o[nt][3] *= a1;
        }

        const int pOff = 32768 + warp * 2048;
        #pragma unroll
        for (int nt = 0; nt < 8; nt++) {
            *(unsigned*)(sm + pOff + SWR(g,     nt * 16 + 4 * t)) =
                packh2(s[nt][0], s[nt][1]);
            *(unsigned*)(sm + pOff + SWR(g + 8, nt * 16 + 4 * t)) =
                packh2(s[nt][2], s[nt][3]);
        }
        __syncwarp();

        const uint32_t pB = smb + pOff;
        #pragma unroll
        for (int ks = 0; ks < 4; ks++) {
            unsigned pf[4];
            LDSM4(pf[0], pf[1], pf[2], pf[3],
                  pB + SWR(arow16, ks * 32 + acol16));
            unsigned vf[8][2];
            #pragma unroll
            for (int np = 0; np < 4; np++) {
                unsigned r0, r1, r2, r3;
                LDSM4T(r0, r1, r2, r3,
                       vbuf + SWR(ks * 16 + ((lane >> 3) & 1) * 8 + (lane & 7),
                                  np * 32 + (lane >> 4) * 16));
                vf[np * 2][0] = r0;      vf[np * 2][1] = r1;
                vf[np * 2 + 1][0] = r2;  vf[np * 2 + 1][1] = r3;
            }
            #pragma unroll
            for (int nt = 0; nt < 8; nt++)
                mma_f16(o[nt], pf, vf[nt]);
        }
    }

    {
        const float inv0 = 1.f / l0;
        const float inv1 = 1.f / l1;
        __half* ob = att + (size_t)b * TT * HH
                   + (size_t)(qt * 128 + warp * 16) * HH + h * HD;
        #pragma unroll
        for (int nt = 0; nt < 8; nt++) {
            const int c = nt * 8 + 2 * t;
            *(unsigned*)&ob[(size_t)g * HH + c] =
                packh2(o[nt][0] * inv0, o[nt][1] * inv0);
            *(unsigned*)&ob[(size_t)(g + 8) * HH + c] =
                packh2(o[nt][2] * inv1, o[nt][3] * inv1);
        }
    }
}

// ---------------------------------------------------------------------------

extern "C" void kernel_launch(void* const* d_in, const int* in_sizes, int n_in,
                              void* d_out, int out_size)
{
    const float*         inp   = (const float*)d_in[0];
    const unsigned char* mask  = (const unsigned char*)d_in[1];
    const float*         w_qkv = (const float*)d_in[2];
    const float*         b_qkv = (const float*)d_in[3];
    const float*         w_out = (const float*)d_in[4];
    const float*         b_out = (const float*)d_in[5];
    float*               out   = (float*)d_out;

    __half *qkv_p, *att_p, *xr_p, *wqT_p, *woT_p;
    cudaGetSymbolAddress((void**)&qkv_p, g_qkv);
    cudaGetSymbolAddress((void**)&att_p, g_att);
    cudaGetSymbolAddress((void**)&xr_p,  g_xr);
    cudaGetSymbolAddress((void**)&wqT_p, g_wqT);
    cudaGetSymbolAddress((void**)&woT_p, g_woT);

    cudaFuncSetAttribute(attn_h,
                         cudaFuncAttributeMaxDynamicSharedMemorySize, AT_SMEM);
    cudaFuncSetAttribute(hgemm<true>,
                         cudaFuncAttributeMaxDynamicSharedMemorySize, TG_SMEM);
    cudaFuncSetAttribute(hgemm<false>,
                         cudaFuncAttributeMaxDynamicSharedMemorySize, TG_SMEM);

    prep_kernel<<<PREP_BLOCKS, 256>>>(mask, inp, w_qkv, w_out,
                                      xr_p, wqT_p, woT_p);

    hgemm<true><<<dim3(H3 / 128, (BB * TT) / 128), 128, TG_SMEM>>>(
        xr_p, wqT_p, b_qkv, qkv_p, BB * TT, H3, HH);
    attn_h<<<dim3(TT / 128, BB * NH), 256, AT_SMEM>>>(qkv_p, att_p);
    hgemm<false><<<dim3(HH / 128, (BB * TT) / 128), 128, TG_SMEM>>>(
        att_p, woT_p, b_out, out, BB * TT, HH, HH);
}

// round 14
// speedup vs baseline: 1.3399x; 1.3399x over previous
#include <cuda_runtime.h>
#include <cuda_fp16.h>
#include <math.h>
#include <stdint.h>

#define BB 4
#define TT 2048
#define HH 1024
#define NH 16
#define HD 64
#define H3 3072

// Scratch (allocation-free rule: __device__ globals)
__device__ __half g_qkv[(size_t)BB * TT * H3];  // (B,T,3H) fp16
__device__ __half g_att[(size_t)BB * TT * HH];  // (B,T,H)  fp16
__device__ __half g_xr [(size_t)BB * TT * HH];  // input fp16
__device__ __half g_wqT[(size_t)H3 * HH];       // w_qkv^T (3H,H) fp16
__device__ __half g_woT[(size_t)HH * HH];       // w_out^T (H,H) fp16
__device__ int    g_len[BB];

// ---------------------------------------------------------------------------
// helpers
// ---------------------------------------------------------------------------
__device__ __forceinline__ void mma_f16(
    float* d, const unsigned* a, const unsigned* b)
{
    asm volatile(
        "mma.sync.aligned.m16n8k16.row.col.f32.f16.f16.f32 "
        "{%0,%1,%2,%3}, {%4,%5,%6,%7}, {%8,%9}, {%0,%1,%2,%3};\n"
        : "+f"(d[0]), "+f"(d[1]), "+f"(d[2]), "+f"(d[3])
        : "r"(a[0]), "r"(a[1]), "r"(a[2]), "r"(a[3]),
          "r"(b[0]), "r"(b[1]));
}

__device__ __forceinline__ uint32_t smem_u32(const void* p) {
    uint32_t a;
    asm("{ .reg .u64 t; cvta.to.shared.u64 t, %1; cvt.u32.u64 %0, t; }"
        : "=r"(a) : "l"(p));
    return a;
}

__device__ __forceinline__ unsigned packh2(float a, float b) {
    __half2 h = __floats2half2_rn(a, b);
    return *(unsigned*)&h;
}

// L2-only global->smem copy (no L1 allocation; tiles have zero L1 reuse)
#define CP16(dst, src) \
    asm volatile("cp.async.cg.shared.global [%0], [%1], 16;" \
                 :: "r"(dst), "l"(src) : "memory")
#define CPCOMMIT() asm volatile("cp.async.commit_group;" ::: "memory")

#define LDSM4(r0, r1, r2, r3, addr) \
    asm volatile("ldmatrix.sync.aligned.m8n8.x4.shared.b16 {%0,%1,%2,%3}, [%4];" \
                 : "=r"(r0), "=r"(r1), "=r"(r2), "=r"(r3) : "r"(addr))

#define LDSM4T(r0, r1, r2, r3, addr) \
    asm volatile("ldmatrix.sync.aligned.m8n8.x4.trans.shared.b16 {%0,%1,%2,%3}, [%4];" \
                 : "=r"(r0), "=r"(r1), "=r"(r2), "=r"(r3) : "r"(addr))

// SW128 swizzle on 16B granules within a 128B row
#define SWR(row, byteoff) (((row) * 128 + (byteoff)) ^ (((row) & 7) << 4))

// ---------------------------------------------------------------------------
// Fused prepass: len + input cvt + both weight transposes, one launch.
// ---------------------------------------------------------------------------
#define PREP_CVT0   4
#define PREP_CVTN   2048
#define PREP_TQ0    (PREP_CVT0 + PREP_CVTN)          // 2052
#define PREP_TQN    ((H3 / 32) * (HH / 32))          // 3072
#define PREP_TO0    (PREP_TQ0 + PREP_TQN)            // 5124
#define PREP_TON    ((HH / 32) * (HH / 32))          // 1024
#define PREP_BLOCKS (PREP_TO0 + PREP_TON)            // 6148

__global__ void prep_kernel(
    const unsigned char* __restrict__ mask, const float* __restrict__ inp,
    const float* __restrict__ w_qkv, const float* __restrict__ w_out,
    __half* __restrict__ xr, __half* __restrict__ wqT, __half* __restrict__ woT)
{
    __shared__ float sf[32][33];
    const int bid = blockIdx.x;
    const int tid = threadIdx.x;

    if (bid < 4) {
        __shared__ int sred[256];
        const unsigned int w0 = *(const unsigned int*)mask;
        const int b = bid;
        int cnt = 0;
        if (w0 == 0x01010101u) {
            for (int t = tid; t < TT; t += 256)
                cnt += (mask[(size_t)b * TT + t] != 0) ? 1 : 0;
        } else if (w0 == 0x3F800000u) {
            const float* m = (const float*)mask;
            for (int t = tid; t < TT; t += 256)
                cnt += (m[(size_t)b * TT + t] != 0.f) ? 1 : 0;
        } else {
            const int* m = (const int*)mask;
            for (int t = tid; t < TT; t += 256)
                cnt += (m[(size_t)b * TT + t] != 0) ? 1 : 0;
        }
        sred[tid] = cnt;
        __syncthreads();
        for (int s = 128; s > 0; s >>= 1) {
            if (tid < s) sred[tid] += sred[tid + s];
            __syncthreads();
        }
        if (tid == 0) g_len[b] = sred[0];
    } else if (bid < PREP_TQ0) {
        const float4* in = (const float4*)inp;
        uint2* out = (uint2*)xr;
        const int n4 = (BB * TT * HH) / 4;
        for (int i = (bid - PREP_CVT0) * 256 + tid; i < n4;
             i += PREP_CVTN * 256) {
            float4 v = in[i];
            out[i] = make_uint2(packh2(v.x, v.y), packh2(v.z, v.w));
        }
    } else {
        const float* S;
        __half* D;
        int R, C, tb;
        if (bid < PREP_TO0) {
            S = w_qkv; D = wqT; R = HH; C = H3; tb = bid - PREP_TQ0;
        } else {
            S = w_out; D = woT; R = HH; C = HH; tb = bid - PREP_TO0;
        }
        const int nbx = C / 32;
        const int bx = tb % nbx;
        const int by = tb / nbx;
        const int tx = tid & 31;
        const int ty = tid >> 5;
        const int x = bx * 32 + tx;
        const int y0 = by * 32;
        #pragma unroll
        for (int i = ty; i < 32; i += 8)
            sf[i][tx] = S[(size_t)(y0 + i) * C + x];
        __syncthreads();
        const int xo = y0 + tx;
        const int yo0 = bx * 32;
        #pragma unroll
        for (int i = ty; i < 32; i += 8)
            D[(size_t)(yo0 + i) * R + xo] = __float2half_rn(sf[tx][i]);
    }
}

// ---------------------------------------------------------------------------
// fp16 HMMA GEMM (R12-proven geometry): 3-stage cp.async, ONE sync per chunk.
// C(M,N) = A(M,K) @ Bt(N,K)^T + bias(N).  CTA 128x128, K-chunk 64 halves,
// 8 warps (2x4), warp tile 64x32, m16n8k16.  Smem 96KB -> 2 CTAs/SM.
// ---------------------------------------------------------------------------
#define TG_AST  16384
#define TG_SMEM (6 * TG_AST)

template <bool HOUT>
__global__ __launch_bounds__(256) void hgemm(
    const __half* __restrict__ A, const __half* __restrict__ Bt,
    const float* __restrict__ bias, void* __restrict__ Cv,
    int M, int N, int K)
{
    extern __shared__ char smem[];
    const uint32_t base = smem_u32(smem);

    const int tid   = threadIdx.x;
    const int warp  = tid >> 5;
    const int lane  = tid & 31;
    const int g     = lane >> 2;
    const int t     = lane & 3;
    const int warpM = warp & 1;
    const int warpN = warp >> 1;
    const int brow  = blockIdx.y * 128;
    const int bcol  = blockIdx.x * 128;

    uint32_t sA[3], sB[3];
    #pragma unroll
    for (int s = 0; s < 3; s++) {
        sA[s] = base + s * TG_AST;
        sB[s] = base + 3 * TG_AST + s * TG_AST;
    }

    // loader: row tid/2, granules (tid&1)*4 + q  (granule = 16B = 8 halves)
    const int lrow = tid >> 1;
    const int lg   = (tid & 1) * 4;
    const __half* Ap = A  + (size_t)(brow + lrow) * K + lg * 8;
    const __half* Bp = Bt + (size_t)(bcol + lrow) * K + lg * 8;
    uint32_t swl[4];
    #pragma unroll
    for (int q = 0; q < 4; q++) swl[q] = SWR(lrow, (lg + q) * 16);

    // consumer lane maps
    const int arow16 = lane & 15;
    const int acol16 = (lane >> 4) * 16;
    const int brow_i = (lane & 7) + (lane >> 4) * 8;
    const int bcol_i = ((lane >> 3) & 1) * 16;

    float acc[4][4][4];
    #pragma unroll
    for (int i = 0; i < 4; i++)
        #pragma unroll
        for (int j = 0; j < 4; j++)
            #pragma unroll
            for (int q = 0; q < 4; q++) acc[i][j][q] = 0.f;

    const int nch = K >> 6;   // 64-half chunks

    // prologue: chunks 0,1 -> stages 0,1
    #pragma unroll
    for (int pc = 0; pc < 2; pc++) {
        #pragma unroll
        for (int q = 0; q < 4; q++) {
            CP16(sA[pc] + swl[q], Ap + pc * 64 + q * 8);
            CP16(sB[pc] + swl[q], Bp + pc * 64 + q * 8);
        }
        CPCOMMIT();
    }

    int st = 0, sp = 2;
    for (int kc = 0; kc < nch; kc++) {
        if (kc < nch - 1)
            asm volatile("cp.async.wait_group 1;" ::: "memory");
        else
            asm volatile("cp.async.wait_group 0;" ::: "memory");
        __syncthreads();

        if (kc + 2 < nch) {
            const __half* Ap2 = Ap + (kc + 2) * 64;
            const __half* Bp2 = Bp + (kc + 2) * 64;
            #pragma unroll
            for (int q = 0; q < 4; q++) {
                CP16(sA[sp] + swl[q], Ap2 + q * 8);
                CP16(sB[sp] + swl[q], Bp2 + q * 8);
            }
            CPCOMMIT();
        }

        const uint32_t aBase = sA[st];
        const uint32_t bBase = sB[st];

        #pragma unroll
        for (int ks = 0; ks < 4; ks++) {
            const int kb = ks * 32;   // k16 sub-chunk = 32 bytes
            unsigned af[4][4];
            #pragma unroll
            for (int mt = 0; mt < 4; mt++) {
                const int r = warpM * 64 + mt * 16 + arow16;
                LDSM4(af[mt][0], af[mt][1], af[mt][2], af[mt][3],
                      aBase + SWR(r, kb + acol16));
            }
            unsigned bf[4][2];
            #pragma unroll
            for (int np = 0; np < 2; np++) {
                const int r = warpN * 32 + np * 16 + brow_i;
                unsigned r0, r1, r2, r3;
                LDSM4(r0, r1, r2, r3, bBase + SWR(r, kb + bcol_i));
                bf[np * 2][0] = r0;      bf[np * 2][1] = r1;
                bf[np * 2 + 1][0] = r2;  bf[np * 2 + 1][1] = r3;
            }
            #pragma unroll
            for (int mt = 0; mt < 4; mt++)
                #pragma unroll
                for (int nt = 0; nt < 4; nt++)
                    mma_f16(acc[mt][nt], af[mt], bf[nt]);
        }

        st = (st == 2) ? 0 : st + 1;
        sp = (sp == 2) ? 0 : sp + 1;
    }

    // epilogue: bias + store
    #pragma unroll
    for (int mt = 0; mt < 4; mt++) {
        const int r0 = brow + warpM * 64 + mt * 16 + g;
        #pragma unroll
        for (int nt = 0; nt < 4; nt++) {
            const int c = bcol + warpN * 32 + nt * 8 + 2 * t;
            const float bv0 = bias[c], bv1 = bias[c + 1];
            if (HOUT) {
                __half* C = (__half*)Cv;
                *(unsigned*)&C[(size_t)r0 * N + c] =
                    packh2(acc[mt][nt][0] + bv0, acc[mt][nt][1] + bv1);
                *(unsigned*)&C[(size_t)(r0 + 8) * N + c] =
                    packh2(acc[mt][nt][2] + bv0, acc[mt][nt][3] + bv1);
            } else {
                float* C = (float*)Cv;
                float2 v0 = {acc[mt][nt][0] + bv0, acc[mt][nt][1] + bv1};
                float2 v1 = {acc[mt][nt][2] + bv0, acc[mt][nt][3] + bv1};
                *(float2*)&C[(size_t)r0 * N + c]       = v0;
                *(float2*)&C[(size_t)(r0 + 8) * N + c] = v1;
            }
        }
    }
}

// ---------------------------------------------------------------------------
// FA2 fp16 attention (R11-proven, unchanged)
// ---------------------------------------------------------------------------
#define AT_SMEM 49152

__global__ __launch_bounds__(256) void attn_h(
    const __half* __restrict__ qkv, __half* __restrict__ att)
{
    extern __shared__ char sm[];
    const uint32_t smb = smem_u32(sm);

    const int tid  = threadIdx.x;
    const int warp = tid >> 5;
    const int lane = tid & 31;
    const int g = lane >> 2;
    const int t = lane & 3;
    const int qt = blockIdx.x;
    const int b  = blockIdx.y >> 4;
    const int h  = blockIdx.y & 15;
    const int len = g_len[b];

    const __half* qb = qkv + (size_t)b * TT * H3 + h * HD;
    const __half* kb = qb + HH;
    const __half* vb = qb + 2 * HH;

    {
        const int r = tid >> 1;
        #pragma unroll
        for (int q = 0; q < 4; q++) {
            const int gq = (tid & 1) * 4 + q;
            uint4 v = *(const uint4*)(qb + (size_t)(qt * 128 + r) * H3 + gq * 8);
            *(uint4*)(sm + SWR(r, gq * 16)) = v;
        }
    }
    __syncthreads();

    const int arow16 = lane & 15;
    const int acol16 = (lane >> 4) * 16;
    const int brow_i = (lane & 7) + (lane >> 4) * 8;
    const int bcol_i = ((lane >> 3) & 1) * 16;

    unsigned qf[4][4];
    #pragma unroll
    for (int ks = 0; ks < 4; ks++)
        LDSM4(qf[ks][0], qf[ks][1], qf[ks][2], qf[ks][3],
              smb + SWR(warp * 16 + arow16, ks * 32 + acol16));
    __syncthreads();

    float m0 = -1e30f, m1 = -1e30f, l0 = 0.f, l1 = 0.f;
    float o[8][4];
    #pragma unroll
    for (int nt = 0; nt < 8; nt++)
        #pragma unroll
        for (int q = 0; q < 4; q++) o[nt][q] = 0.f;

    const int row0 = qt * 128 + warp * 16 + g;
    const int kt_max = min(2 * qt + 1, (len - 1) >> 6);

    const int rv  = tid >> 2;
    const int gk0 = (tid & 3) * 2;

    uint4 kreg[2], vreg[2];
    #pragma unroll
    for (int j = 0; j < 2; j++) {
        kreg[j] = *(const uint4*)(kb + (size_t)rv * H3 + (gk0 + j) * 8);
        vreg[j] = *(const uint4*)(vb + (size_t)rv * H3 + (gk0 + j) * 8);
    }

    for (int kt = 0; kt <= kt_max; kt++) {
        const int buf = kt & 1;
        const uint32_t kbuf = smb + buf * 8192;
        const uint32_t vbuf = smb + 16384 + buf * 8192;

        #pragma unroll
        for (int j = 0; j < 2; j++) {
            *(uint4*)(sm + buf * 8192 + SWR(rv, (gk0 + j) * 16)) = kreg[j];
            *(uint4*)(sm + 16384 + buf * 8192 + SWR(rv, (gk0 + j) * 16)) = vreg[j];
        }
        __syncthreads();

        if (kt < kt_max) {
            #pragma unroll
            for (int j = 0; j < 2; j++) {
                const size_t ro = (size_t)((kt + 1) * 64 + rv) * H3 + (gk0 + j) * 8;
                kreg[j] = *(const uint4*)(kb + ro);
                vreg[j] = *(const uint4*)(vb + ro);
            }
        }

        float s[8][4];
        #pragma unroll
        for (int nt = 0; nt < 8; nt++)
            #pragma unroll
            for (int q = 0; q < 4; q++) s[nt][q] = 0.f;

        #pragma unroll
        for (int ks = 0; ks < 4; ks++) {
            unsigned bf[8][2];
            #pragma unroll
            for (int np = 0; np < 4; np++) {
                unsigned r0, r1, r2, r3;
                LDSM4(r0, r1, r2, r3,
                      kbuf + SWR(np * 16 + brow_i, ks * 32 + bcol_i));
                bf[np * 2][0] = r0;      bf[np * 2][1] = r1;
                bf[np * 2 + 1][0] = r2;  bf[np * 2 + 1][1] = r3;
            }
            #pragma unroll
            for (int nt = 0; nt < 8; nt++)
                mma_f16(s[nt], qf[ks], bf[nt]);
        }

        #pragma unroll
        for (int nt = 0; nt < 8; nt++) {
            const int c0 = kt * 64 + nt * 8 + 2 * t;
            s[nt][0] = (c0     <= row0     && c0     < len) ? s[nt][0] * 0.125f : -1e30f;
            s[nt][1] = (c0 + 1 <= row0     && c0 + 1 < len) ? s[nt][1] * 0.125f : -1e30f;
            s[nt][2] = (c0     <= row0 + 8 && c0     < len) ? s[nt][2] * 0.125f : -1e30f;
            s[nt][3] = (c0 + 1 <= row0 + 8 && c0 + 1 < len) ? s[nt][3] * 0.125f : -1e30f;
        }

        float mx0 = -1e30f, mx1 = -1e30f;
        #pragma unroll
        for (int nt = 0; nt < 8; nt++) {
            mx0 = fmaxf(mx0, fmaxf(s[nt][0], s[nt][1]));
            mx1 = fmaxf(mx1, fmaxf(s[nt][2], s[nt][3]));
        }
        mx0 = fmaxf(mx0, __shfl_xor_sync(0xffffffffu, mx0, 1));
        mx0 = fmaxf(mx0, __shfl_xor_sync(0xffffffffu, mx0, 2));
        mx1 = fmaxf(mx1, __shfl_xor_sync(0xffffffffu, mx1, 1));
        mx1 = fmaxf(mx1, __shfl_xor_sync(0xffffffffu, mx1, 2));

        const float mn0 = fmaxf(m0, mx0);
        const float mn1 = fmaxf(m1, mx1);
        const float a0 = __expf(m0 - mn0);
        const float a1 = __expf(m1 - mn1);
        m0 = mn0; m1 = mn1;

        float sum0 = 0.f, sum1 = 0.f;
        #pragma unroll
        for (int nt = 0; nt < 8; nt++) {
            s[nt][0] = __expf(s[nt][0] - mn0);
            s[nt][1] = __expf(s[nt][1] - mn0);
            s[nt][2] = __expf(s[nt][2] - mn1);
            s[nt][3] = __expf(s[nt][3] - mn1);
            sum0 += s[nt][0] + s[nt][1];
            sum1 += s[nt][2] + s[nt][3];
        }
        sum0 += __shfl_xor_sync(0xffffffffu, sum0, 1);
        sum0 += __shfl_xor_sync(0xffffffffu, sum0, 2);
        sum1 += __shfl_xor_sync(0xffffffffu, sum1, 1);
        sum1 += __shfl_xor_sync(0xffffffffu, sum1, 2);
        l0 = l0 * a0 + sum0;
        l1 = l1 * a1 + sum1;

        #pragma unroll
        for (int nt = 0; nt < 8; nt++) {
            o[nt][0] *= a0; o[nt][1] *= a0;
            o[nt][2] *= a1; o[nt][3] *= a1;
        }

        const int pOff = 32768 + warp * 2048;
        #pragma unroll
        for (int nt = 0; nt < 8; nt++) {
            *(unsigned*)(sm + pOff + SWR(g,     nt * 16 + 4 * t)) =
                packh2(s[nt][0], s[nt][1]);
            *(unsigned*)(sm + pOff + SWR(g + 8, nt * 16 + 4 * t)) =
                packh2(s[nt][2], s[nt][3]);
        }
        __syncwarp();

        const uint32_t pB = smb + pOff;
        #pragma unroll
        for (int ks = 0; ks < 4; ks++) {
            unsigned pf[4];
            LDSM4(pf[0], pf[1], pf[2], pf[3],
                  pB + SWR(arow16, ks * 32 + acol16));
            unsigned vf[8][2];
            #pragma unroll
            for (int np = 0; np < 4; np++) {
                unsigned r0, r1, r2, r3;
                LDSM4T(r0, r1, r2, r3,
                       vbuf + SWR(ks * 16 + ((lane >> 3) & 1) * 8 + (lane & 7),
                                  np * 32 + (lane >> 4) * 16));
                vf[np * 2][0] = r0;      vf[np * 2][1] = r1;
                vf[np * 2 + 1][0] = r2;  vf[np * 2 + 1][1] = r3;
            }
            #pragma unroll
            for (int nt = 0; nt < 8; nt++)
                mma_f16(o[nt], pf, vf[nt]);
        }
    }

    {
        const float inv0 = 1.f / l0;
        const float inv1 = 1.f / l1;
        __half* ob = att + (size_t)b * TT * HH
                   + (size_t)(qt * 128 + warp * 16) * HH + h * HD;
        #pragma unroll
        for (int nt = 0; nt < 8; nt++) {
            const int c = nt * 8 + 2 * t;
            *(unsigned*)&ob[(size_t)g * HH + c] =
                packh2(o[nt][0] * inv0, o[nt][1] * inv0);
            *(unsigned*)&ob[(size_t)(g + 8) * HH + c] =
                packh2(o[nt][2] * inv1, o[nt][3] * inv1);
        }
    }
}

// ---------------------------------------------------------------------------

extern "C" void kernel_launch(void* const* d_in, const int* in_sizes, int n_in,
                              void* d_out, int out_size)
{
    const float*         inp   = (const float*)d_in[0];
    const unsigned char* mask  = (const unsigned char*)d_in[1];
    const float*         w_qkv = (const float*)d_in[2];
    const float*         b_qkv = (const float*)d_in[3];
    const float*         w_out = (const float*)d_in[4];
    const float*         b_out = (const float*)d_in[5];
    float*               out   = (float*)d_out;

    __half *qkv_p, *att_p, *xr_p, *wqT_p, *woT_p;
    cudaGetSymbolAddress((void**)&qkv_p, g_qkv);
    cudaGetSymbolAddress((void**)&att_p, g_att);
    cudaGetSymbolAddress((void**)&xr_p,  g_xr);
    cudaGetSymbolAddress((void**)&wqT_p, g_wqT);
    cudaGetSymbolAddress((void**)&woT_p, g_woT);

    cudaFuncSetAttribute(attn_h,
                         cudaFuncAttributeMaxDynamicSharedMemorySize, AT_SMEM);
    cudaFuncSetAttribute(hgemm<true>,
                         cudaFuncAttributeMaxDynamicSharedMemorySize, TG_SMEM);
    cudaFuncSetAttribute(hgemm<false>,
                         cudaFuncAttributeMaxDynamicSharedMemorySize, TG_SMEM);

    prep_kernel<<<PREP_BLOCKS, 256>>>(mask, inp, w_qkv, w_out,
                                      xr_p, wqT_p, woT_p);

    hgemm<true><<<dim3(H3 / 128, (BB * TT) / 128), 256, TG_SMEM>>>(
        xr_p, wqT_p, b_qkv, qkv_p, BB * TT, H3, HH);
    attn_h<<<dim3(TT / 128, BB * NH), 256, AT_SMEM>>>(qkv_p, att_p);
    hgemm<false><<<dim3(HH / 128, (BB * TT) / 128), 256, TG_SMEM>>>(
        att_p, woT_p, b_out, out, BB * TT, HH, HH);
}

// round 15
// speedup vs baseline: 1.3886x; 1.0364x over previous
#include <cuda_runtime.h>
#include <cuda_fp16.h>
#include <math.h>
#include <stdint.h>

#define BB 4
#define TT 2048
#define HH 1024
#define NH 16
#define HD 64
#define H3 3072

// Scratch (allocation-free rule: __device__ globals)
__device__ __half g_qkv[(size_t)BB * TT * H3];  // (B,T,3H) fp16
__device__ __half g_att[(size_t)BB * TT * HH];  // (B,T,H)  fp16
__device__ __half g_xr [(size_t)BB * TT * HH];  // input fp16
__device__ __half g_wqT[(size_t)H3 * HH];       // w_qkv^T (3H,H) fp16
__device__ __half g_woT[(size_t)HH * HH];       // w_out^T (H,H) fp16
__device__ int    g_len[BB];

// ---------------------------------------------------------------------------
// helpers
// ---------------------------------------------------------------------------
__device__ __forceinline__ void mma_f16(
    float* d, const unsigned* a, const unsigned* b)
{
    asm volatile(
        "mma.sync.aligned.m16n8k16.row.col.f32.f16.f16.f32 "
        "{%0,%1,%2,%3}, {%4,%5,%6,%7}, {%8,%9}, {%0,%1,%2,%3};\n"
        : "+f"(d[0]), "+f"(d[1]), "+f"(d[2]), "+f"(d[3])
        : "r"(a[0]), "r"(a[1]), "r"(a[2]), "r"(a[3]),
          "r"(b[0]), "r"(b[1]));
}

__device__ __forceinline__ uint32_t smem_u32(const void* p) {
    uint32_t a;
    asm("{ .reg .u64 t; cvta.to.shared.u64 t, %1; cvt.u32.u64 %0, t; }"
        : "=r"(a) : "l"(p));
    return a;
}

__device__ __forceinline__ unsigned packh2(float a, float b) {
    __half2 h = __floats2half2_rn(a, b);
    return *(unsigned*)&h;
}

// L2-only global->smem copy (no L1 allocation; tiles have zero L1 reuse)
#define CP16(dst, src) \
    asm volatile("cp.async.cg.shared.global [%0], [%1], 16;" \
                 :: "r"(dst), "l"(src) : "memory")
#define CPCOMMIT() asm volatile("cp.async.commit_group;" ::: "memory")

#define LDSM4(r0, r1, r2, r3, addr) \
    asm volatile("ldmatrix.sync.aligned.m8n8.x4.shared.b16 {%0,%1,%2,%3}, [%4];" \
                 : "=r"(r0), "=r"(r1), "=r"(r2), "=r"(r3) : "r"(addr))

#define LDSM4T(r0, r1, r2, r3, addr) \
    asm volatile("ldmatrix.sync.aligned.m8n8.x4.trans.shared.b16 {%0,%1,%2,%3}, [%4];" \
                 : "=r"(r0), "=r"(r1), "=r"(r2), "=r"(r3) : "r"(addr))

// SW128 swizzle on 16B granules within a 128B row
#define SWR(row, byteoff) (((row) * 128 + (byteoff)) ^ (((row) & 7) << 4))

// ---------------------------------------------------------------------------
// Fused prepass: len + input cvt + both weight transposes, one launch.
// ---------------------------------------------------------------------------
#define PREP_CVT0   4
#define PREP_CVTN   2048
#define PREP_TQ0    (PREP_CVT0 + PREP_CVTN)          // 2052
#define PREP_TQN    ((H3 / 32) * (HH / 32))          // 3072
#define PREP_TO0    (PREP_TQ0 + PREP_TQN)            // 5124
#define PREP_TON    ((HH / 32) * (HH / 32))          // 1024
#define PREP_BLOCKS (PREP_TO0 + PREP_TON)            // 6148

__global__ void prep_kernel(
    const unsigned char* __restrict__ mask, const float* __restrict__ inp,
    const float* __restrict__ w_qkv, const float* __restrict__ w_out,
    __half* __restrict__ xr, __half* __restrict__ wqT, __half* __restrict__ woT)
{
    __shared__ float sf[32][33];
    const int bid = blockIdx.x;
    const int tid = threadIdx.x;

    if (bid < 4) {
        __shared__ int sred[256];
        const unsigned int w0 = *(const unsigned int*)mask;
        const int b = bid;
        int cnt = 0;
        if (w0 == 0x01010101u) {
            for (int t = tid; t < TT; t += 256)
                cnt += (mask[(size_t)b * TT + t] != 0) ? 1 : 0;
        } else if (w0 == 0x3F800000u) {
            const float* m = (const float*)mask;
            for (int t = tid; t < TT; t += 256)
                cnt += (m[(size_t)b * TT + t] != 0.f) ? 1 : 0;
        } else {
            const int* m = (const int*)mask;
            for (int t = tid; t < TT; t += 256)
                cnt += (m[(size_t)b * TT + t] != 0) ? 1 : 0;
        }
        sred[tid] = cnt;
        __syncthreads();
        for (int s = 128; s > 0; s >>= 1) {
            if (tid < s) sred[tid] += sred[tid + s];
            __syncthreads();
        }
        if (tid == 0) g_len[b] = sred[0];
    } else if (bid < PREP_TQ0) {
        const float4* in = (const float4*)inp;
        uint2* out = (uint2*)xr;
        const int n4 = (BB * TT * HH) / 4;
        for (int i = (bid - PREP_CVT0) * 256 + tid; i < n4;
             i += PREP_CVTN * 256) {
            float4 v = in[i];
            out[i] = make_uint2(packh2(v.x, v.y), packh2(v.z, v.w));
        }
    } else {
        const float* S;
        __half* D;
        int R, C, tb;
        if (bid < PREP_TO0) {
            S = w_qkv; D = wqT; R = HH; C = H3; tb = bid - PREP_TQ0;
        } else {
            S = w_out; D = woT; R = HH; C = HH; tb = bid - PREP_TO0;
        }
        const int nbx = C / 32;
        const int bx = tb % nbx;
        const int by = tb / nbx;
        const int tx = tid & 31;
        const int ty = tid >> 5;
        const int x = bx * 32 + tx;
        const int y0 = by * 32;
        #pragma unroll
        for (int i = ty; i < 32; i += 8)
            sf[i][tx] = S[(size_t)(y0 + i) * C + x];
        __syncthreads();
        const int xo = y0 + tx;
        const int yo0 = bx * 32;
        #pragma unroll
        for (int i = ty; i < 32; i += 8)
            D[(size_t)(yo0 + i) * R + xo] = __float2half_rn(sf[tx][i]);
    }
}

// ---------------------------------------------------------------------------
// fp16 HMMA GEMM (R14-proven): 3-stage cp.async.cg, ONE sync per chunk.
// C(M,N) = A(M,K) @ Bt(N,K)^T + bias(N).  CTA 128x128, K-chunk 64 halves,
// 8 warps (2x4), warp tile 64x32, m16n8k16.  Smem 96KB -> 2 CTAs/SM.
// LENSKIP: early-exit CTAs computing K/V rows for padded tokens
// (bcol >= HH and all 128 rows >= ceil64(len[b])) — outputs never read.
// ---------------------------------------------------------------------------
#define TG_AST  16384
#define TG_SMEM (6 * TG_AST)

template <bool HOUT, bool LENSKIP>
__global__ __launch_bounds__(256) void hgemm(
    const __half* __restrict__ A, const __half* __restrict__ Bt,
    const float* __restrict__ bias, void* __restrict__ Cv,
    int M, int N, int K)
{
    extern __shared__ char smem[];
    const uint32_t base = smem_u32(smem);

    const int brow  = blockIdx.y * 128;
    const int bcol  = blockIdx.x * 128;

    if (LENSKIP) {
        // rows beyond ceil64(len) feed only masked-out K/V columns
        const int b  = brow >> 11;          // row / 2048
        const int t0 = brow & 2047;
        const int lb = (g_len[b] + 63) & ~63;
        if (bcol >= HH && t0 >= lb) return;
    }

    const int tid   = threadIdx.x;
    const int warp  = tid >> 5;
    const int lane  = tid & 31;
    const int g     = lane >> 2;
    const int t     = lane & 3;
    const int warpM = warp & 1;
    const int warpN = warp >> 1;

    uint32_t sA[3], sB[3];
    #pragma unroll
    for (int s = 0; s < 3; s++) {
        sA[s] = base + s * TG_AST;
        sB[s] = base + 3 * TG_AST + s * TG_AST;
    }

    // loader: row tid/2, granules (tid&1)*4 + q  (granule = 16B = 8 halves)
    const int lrow = tid >> 1;
    const int lg   = (tid & 1) * 4;
    const __half* Ap = A  + (size_t)(brow + lrow) * K + lg * 8;
    const __half* Bp = Bt + (size_t)(bcol + lrow) * K + lg * 8;
    uint32_t swl[4];
    #pragma unroll
    for (int q = 0; q < 4; q++) swl[q] = SWR(lrow, (lg + q) * 16);

    // consumer lane maps
    const int arow16 = lane & 15;
    const int acol16 = (lane >> 4) * 16;
    const int brow_i = (lane & 7) + (lane >> 4) * 8;
    const int bcol_i = ((lane >> 3) & 1) * 16;

    float acc[4][4][4];
    #pragma unroll
    for (int i = 0; i < 4; i++)
        #pragma unroll
        for (int j = 0; j < 4; j++)
            #pragma unroll
            for (int q = 0; q < 4; q++) acc[i][j][q] = 0.f;

    const int nch = K >> 6;   // 64-half chunks

    // prologue: chunks 0,1 -> stages 0,1
    #pragma unroll
    for (int pc = 0; pc < 2; pc++) {
        #pragma unroll
        for (int q = 0; q < 4; q++) {
            CP16(sA[pc] + swl[q], Ap + pc * 64 + q * 8);
            CP16(sB[pc] + swl[q], Bp + pc * 64 + q * 8);
        }
        CPCOMMIT();
    }

    int st = 0, sp = 2;
    for (int kc = 0; kc < nch; kc++) {
        if (kc < nch - 1)
            asm volatile("cp.async.wait_group 1;" ::: "memory");
        else
            asm volatile("cp.async.wait_group 0;" ::: "memory");
        __syncthreads();

        if (kc + 2 < nch) {
            const __half* Ap2 = Ap + (kc + 2) * 64;
            const __half* Bp2 = Bp + (kc + 2) * 64;
            #pragma unroll
            for (int q = 0; q < 4; q++) {
                CP16(sA[sp] + swl[q], Ap2 + q * 8);
                CP16(sB[sp] + swl[q], Bp2 + q * 8);
            }
            CPCOMMIT();
        }

        const uint32_t aBase = sA[st];
        const uint32_t bBase = sB[st];

        #pragma unroll
        for (int ks = 0; ks < 4; ks++) {
            const int kb = ks * 32;   // k16 sub-chunk = 32 bytes
            unsigned af[4][4];
            #pragma unroll
            for (int mt = 0; mt < 4; mt++) {
                const int r = warpM * 64 + mt * 16 + arow16;
                LDSM4(af[mt][0], af[mt][1], af[mt][2], af[mt][3],
                      aBase + SWR(r, kb + acol16));
            }
            unsigned bf[4][2];
            #pragma unroll
            for (int np = 0; np < 2; np++) {
                const int r = warpN * 32 + np * 16 + brow_i;
                unsigned r0, r1, r2, r3;
                LDSM4(r0, r1, r2, r3, bBase + SWR(r, kb + bcol_i));
                bf[np * 2][0] = r0;      bf[np * 2][1] = r1;
                bf[np * 2 + 1][0] = r2;  bf[np * 2 + 1][1] = r3;
            }
            #pragma unroll
            for (int mt = 0; mt < 4; mt++)
                #pragma unroll
                for (int nt = 0; nt < 4; nt++)
                    mma_f16(acc[mt][nt], af[mt], bf[nt]);
        }

        st = (st == 2) ? 0 : st + 1;
        sp = (sp == 2) ? 0 : sp + 1;
    }

    // epilogue: bias + store
    #pragma unroll
    for (int mt = 0; mt < 4; mt++) {
        const int r0 = brow + warpM * 64 + mt * 16 + g;
        #pragma unroll
        for (int nt = 0; nt < 4; nt++) {
            const int c = bcol + warpN * 32 + nt * 8 + 2 * t;
            const float bv0 = bias[c], bv1 = bias[c + 1];
            if (HOUT) {
                __half* C = (__half*)Cv;
                *(unsigned*)&C[(size_t)r0 * N + c] =
                    packh2(acc[mt][nt][0] + bv0, acc[mt][nt][1] + bv1);
                *(unsigned*)&C[(size_t)(r0 + 8) * N + c] =
                    packh2(acc[mt][nt][2] + bv0, acc[mt][nt][3] + bv1);
            } else {
                float* C = (float*)Cv;
                float2 v0 = {acc[mt][nt][0] + bv0, acc[mt][nt][1] + bv1};
                float2 v1 = {acc[mt][nt][2] + bv0, acc[mt][nt][3] + bv1};
                *(float2*)&C[(size_t)r0 * N + c]       = v0;
                *(float2*)&C[(size_t)(r0 + 8) * N + c] = v1;
            }
        }
    }
}

// ---------------------------------------------------------------------------
// FA2 fp16 attention (R11-proven, unchanged)
// ---------------------------------------------------------------------------
#define AT_SMEM 49152

__global__ __launch_bounds__(256) void attn_h(
    const __half* __restrict__ qkv, __half* __restrict__ att)
{
    extern __shared__ char sm[];
    const uint32_t smb = smem_u32(sm);

    const int tid  = threadIdx.x;
    const int warp = tid >> 5;
    const int lane = tid & 31;
    const int g = lane >> 2;
    const int t = lane & 3;
    const int qt = blockIdx.x;
    const int b  = blockIdx.y >> 4;
    const int h  = blockIdx.y & 15;
    const int len = g_len[b];

    const __half* qb = qkv + (size_t)b * TT * H3 + h * HD;
    const __half* kb = qb + HH;
    const __half* vb = qb + 2 * HH;

    {
        const int r = tid >> 1;
        #pragma unroll
        for (int q = 0; q < 4; q++) {
            const int gq = (tid & 1) * 4 + q;
            uint4 v = *(const uint4*)(qb + (size_t)(qt * 128 + r) * H3 + gq * 8);
            *(uint4*)(sm + SWR(r, gq * 16)) = v;
        }
    }
    __syncthreads();

    const int arow16 = lane & 15;
    const int acol16 = (lane >> 4) * 16;
    const int brow_i = (lane & 7) + (lane >> 4) * 8;
    const int bcol_i = ((lane >> 3) & 1) * 16;

    unsigned qf[4][4];
    #pragma unroll
    for (int ks = 0; ks < 4; ks++)
        LDSM4(qf[ks][0], qf[ks][1], qf[ks][2], qf[ks][3],
              smb + SWR(warp * 16 + arow16, ks * 32 + acol16));
    __syncthreads();

    float m0 = -1e30f, m1 = -1e30f, l0 = 0.f, l1 = 0.f;
    float o[8][4];
    #pragma unroll
    for (int nt = 0; nt < 8; nt++)
        #pragma unroll
        for (int q = 0; q < 4; q++) o[nt][q] = 0.f;

    const int row0 = qt * 128 + warp * 16 + g;
    const int kt_max = min(2 * qt + 1, (len - 1) >> 6);

    const int rv  = tid >> 2;
    const int gk0 = (tid & 3) * 2;

    uint4 kreg[2], vreg[2];
    #pragma unroll
    for (int j = 0; j < 2; j++) {
        kreg[j] = *(const uint4*)(kb + (size_t)rv * H3 + (gk0 + j) * 8);
        vreg[j] = *(const uint4*)(vb + (size_t)rv * H3 + (gk0 + j) * 8);
    }

    for (int kt = 0; kt <= kt_max; kt++) {
        const int buf = kt & 1;
        const uint32_t kbuf = smb + buf * 8192;
        const uint32_t vbuf = smb + 16384 + buf * 8192;

        #pragma unroll
        for (int j = 0; j < 2; j++) {
            *(uint4*)(sm + buf * 8192 + SWR(rv, (gk0 + j) * 16)) = kreg[j];
            *(uint4*)(sm + 16384 + buf * 8192 + SWR(rv, (gk0 + j) * 16)) = vreg[j];
        }
        __syncthreads();

        if (kt < kt_max) {
            #pragma unroll
            for (int j = 0; j < 2; j++) {
                const size_t ro = (size_t)((kt + 1) * 64 + rv) * H3 + (gk0 + j) * 8;
                kreg[j] = *(const uint4*)(kb + ro);
                vreg[j] = *(const uint4*)(vb + ro);
            }
        }

        float s[8][4];
        #pragma unroll
        for (int nt = 0; nt < 8; nt++)
            #pragma unroll
            for (int q = 0; q < 4; q++) s[nt][q] = 0.f;

        #pragma unroll
        for (int ks = 0; ks < 4; ks++) {
            unsigned bf[8][2];
            #pragma unroll
            for (int np = 0; np < 4; np++) {
                unsigned r0, r1, r2, r3;
                LDSM4(r0, r1, r2, r3,
                      kbuf + SWR(np * 16 + brow_i, ks * 32 + bcol_i));
                bf[np * 2][0] = r0;      bf[np * 2][1] = r1;
                bf[np * 2 + 1][0] = r2;  bf[np * 2 + 1][1] = r3;
            }
            #pragma unroll
            for (int nt = 0; nt < 8; nt++)
                mma_f16(s[nt], qf[ks], bf[nt]);
        }

        #pragma unroll
        for (int nt = 0; nt < 8; nt++) {
            const int c0 = kt * 64 + nt * 8 + 2 * t;
            s[nt][0] = (c0     <= row0     && c0     < len) ? s[nt][0] * 0.125f : -1e30f;
            s[nt][1] = (c0 + 1 <= row0     && c0 + 1 < len) ? s[nt][1] * 0.125f : -1e30f;
            s[nt][2] = (c0     <= row0 + 8 && c0     < len) ? s[nt][2] * 0.125f : -1e30f;
            s[nt][3] = (c0 + 1 <= row0 + 8 && c0 + 1 < len) ? s[nt][3] * 0.125f : -1e30f;
        }

        float mx0 = -1e30f, mx1 = -1e30f;
        #pragma unroll
        for (int nt = 0; nt < 8; nt++) {
            mx0 = fmaxf(mx0, fmaxf(s[nt][0], s[nt][1]));
            mx1 = fmaxf(mx1, fmaxf(s[nt][2], s[nt][3]));
        }
        mx0 = fmaxf(mx0, __shfl_xor_sync(0xffffffffu, mx0, 1));
        mx0 = fmaxf(mx0, __shfl_xor_sync(0xffffffffu, mx0, 2));
        mx1 = fmaxf(mx1, __shfl_xor_sync(0xffffffffu, mx1, 1));
        mx1 = fmaxf(mx1, __shfl_xor_sync(0xffffffffu, mx1, 2));

        const float mn0 = fmaxf(m0, mx0);
        const float mn1 = fmaxf(m1, mx1);
        const float a0 = __expf(m0 - mn0);
        const float a1 = __expf(m1 - mn1);
        m0 = mn0; m1 = mn1;

        float sum0 = 0.f, sum1 = 0.f;
        #pragma unroll
        for (int nt = 0; nt < 8; nt++) {
            s[nt][0] = __expf(s[nt][0] - mn0);
            s[nt][1] = __expf(s[nt][1] - mn0);
            s[nt][2] = __expf(s[nt][2] - mn1);
            s[nt][3] = __expf(s[nt][3] - mn1);
            sum0 += s[nt][0] + s[nt][1];
            sum1 += s[nt][2] + s[nt][3];
        }
        sum0 += __shfl_xor_sync(0xffffffffu, sum0, 1);
        sum0 += __shfl_xor_sync(0xffffffffu, sum0, 2);
        sum1 += __shfl_xor_sync(0xffffffffu, sum1, 1);
        sum1 += __shfl_xor_sync(0xffffffffu, sum1, 2);
        l0 = l0 * a0 + sum0;
        l1 = l1 * a1 + sum1;

        #pragma unroll
        for (int nt = 0; nt < 8; nt++) {
            o[nt][0] *= a0; o[nt][1] *= a0;
            o[nt][2] *= a1; o[nt][3] *= a1;
        }

        const int pOff = 32768 + warp * 2048;
        #pragma unroll
        for (int nt = 0; nt < 8; nt++) {
            *(unsigned*)(sm + pOff + SWR(g,     nt * 16 + 4 * t)) =
                packh2(s[nt][0], s[nt][1]);
            *(unsigned*)(sm + pOff + SWR(g + 8, nt * 16 + 4 * t)) =
                packh2(s[nt][2], s[nt][3]);
        }
        __syncwarp();

        const uint32_t pB = smb + pOff;
        #pragma unroll
        for (int ks = 0; ks < 4; ks++) {
            unsigned pf[4];
            LDSM4(pf[0], pf[1], pf[2], pf[3],
                  pB + SWR(arow16, ks * 32 + acol16));
            unsigned vf[8][2];
            #pragma unroll
            for (int np = 0; np < 4; np++) {
                unsigned r0, r1, r2, r3;
                LDSM4T(r0, r1, r2, r3,
                       vbuf + SWR(ks * 16 + ((lane >> 3) & 1) * 8 + (lane & 7),
                                  np * 32 + (lane >> 4) * 16));
                vf[np * 2][0] = r0;      vf[np * 2][1] = r1;
                vf[np * 2 + 1][0] = r2;  vf[np * 2 + 1][1] = r3;
            }
            #pragma unroll
            for (int nt = 0; nt < 8; nt++)
                mma_f16(o[nt], pf, vf[nt]);
        }
    }

    {
        const float inv0 = 1.f / l0;
        const float inv1 = 1.f / l1;
        __half* ob = att + (size_t)b * TT * HH
                   + (size_t)(qt * 128 + warp * 16) * HH + h * HD;
        #pragma unroll
        for (int nt = 0; nt < 8; nt++) {
            const int c = nt * 8 + 2 * t;
            *(unsigned*)&ob[(size_t)g * HH + c] =
                packh2(o[nt][0] * inv0, o[nt][1] * inv0);
            *(unsigned*)&ob[(size_t)(g + 8) * HH + c] =
                packh2(o[nt][2] * inv1, o[nt][3] * inv1);
        }
    }
}

// ---------------------------------------------------------------------------

extern "C" void kernel_launch(void* const* d_in, const int* in_sizes, int n_in,
                              void* d_out, int out_size)
{
    const float*         inp   = (const float*)d_in[0];
    const unsigned char* mask  = (const unsigned char*)d_in[1];
    const float*         w_qkv = (const float*)d_in[2];
    const float*         b_qkv = (const float*)d_in[3];
    const float*         w_out = (const float*)d_in[4];
    const float*         b_out = (const float*)d_in[5];
    float*               out   = (float*)d_out;

    __half *qkv_p, *att_p, *xr_p, *wqT_p, *woT_p;
    cudaGetSymbolAddress((void**)&qkv_p, g_qkv);
    cudaGetSymbolAddress((void**)&att_p, g_att);
    cudaGetSymbolAddress((void**)&xr_p,  g_xr);
    cudaGetSymbolAddress((void**)&wqT_p, g_wqT);
    cudaGetSymbolAddress((void**)&woT_p, g_woT);

    cudaFuncSetAttribute(attn_h,
                         cudaFuncAttributeMaxDynamicSharedMemorySize, AT_SMEM);
    cudaFuncSetAttribute((hgemm<true, true>),
                         cudaFuncAttributeMaxDynamicSharedMemorySize, TG_SMEM);
    cudaFuncSetAttribute((hgemm<false, false>),
                         cudaFuncAttributeMaxDynamicSharedMemorySize, TG_SMEM);

    prep_kernel<<<PREP_BLOCKS, 256>>>(mask, inp, w_qkv, w_out,
                                      xr_p, wqT_p, woT_p);

    hgemm<true, true><<<dim3(H3 / 128, (BB * TT) / 128), 256, TG_SMEM>>>(
        xr_p, wqT_p, b_qkv, qkv_p, BB * TT, H3, HH);
    attn_h<<<dim3(TT / 128, BB * NH), 256, AT_SMEM>>>(qkv_p, att_p);
    hgemm<false, false><<<dim3(HH / 128, (BB * TT) / 128), 256, TG_SMEM>>>(
        att_p, woT_p, b_out, out, BB * TT, HH, HH);
}

// round 16
// speedup vs baseline: 1.3990x; 1.0075x over previous
#include <cuda_runtime.h>
#include <cuda_fp16.h>
#include <math.h>
#include <stdint.h>

#define BB 4
#define TT 2048
#define HH 1024
#define NH 16
#define HD 64
#define H3 3072

// Scratch (allocation-free rule: __device__ globals)
__device__ __half g_qkv[(size_t)BB * TT * H3];  // (B,T,3H) fp16
__device__ __half g_att[(size_t)BB * TT * HH];  // (B,T,H)  fp16
__device__ __half g_xr [(size_t)BB * TT * HH];  // input fp16
__device__ __half g_wqT[(size_t)H3 * HH];       // w_qkv^T (3H,H) fp16
__device__ __half g_woT[(size_t)HH * HH];       // w_out^T (H,H) fp16
__device__ int    g_len[BB];

// ---------------------------------------------------------------------------
// helpers
// ---------------------------------------------------------------------------
__device__ __forceinline__ void mma_f16(
    float* d, const unsigned* a, const unsigned* b)
{
    asm volatile(
        "mma.sync.aligned.m16n8k16.row.col.f32.f16.f16.f32 "
        "{%0,%1,%2,%3}, {%4,%5,%6,%7}, {%8,%9}, {%0,%1,%2,%3};\n"
        : "+f"(d[0]), "+f"(d[1]), "+f"(d[2]), "+f"(d[3])
        : "r"(a[0]), "r"(a[1]), "r"(a[2]), "r"(a[3]),
          "r"(b[0]), "r"(b[1]));
}

__device__ __forceinline__ uint32_t smem_u32(const void* p) {
    uint32_t a;
    asm("{ .reg .u64 t; cvta.to.shared.u64 t, %1; cvt.u32.u64 %0, t; }"
        : "=r"(a) : "l"(p));
    return a;
}

__device__ __forceinline__ unsigned packh2(float a, float b) {
    __half2 h = __floats2half2_rn(a, b);
    return *(unsigned*)&h;
}

// L2-only global->smem copy (no L1 allocation; tiles have zero L1 reuse)
#define CP16(dst, src) \
    asm volatile("cp.async.cg.shared.global [%0], [%1], 16;" \
                 :: "r"(dst), "l"(src) : "memory")
#define CPCOMMIT() asm volatile("cp.async.commit_group;" ::: "memory")

#define LDSM4(r0, r1, r2, r3, addr) \
    asm volatile("ldmatrix.sync.aligned.m8n8.x4.shared.b16 {%0,%1,%2,%3}, [%4];" \
                 : "=r"(r0), "=r"(r1), "=r"(r2), "=r"(r3) : "r"(addr))

#define LDSM4T(r0, r1, r2, r3, addr) \
    asm volatile("ldmatrix.sync.aligned.m8n8.x4.trans.shared.b16 {%0,%1,%2,%3}, [%4];" \
                 : "=r"(r0), "=r"(r1), "=r"(r2), "=r"(r3) : "r"(addr))

// SW128 swizzle on 16B granules within a 128B row
#define SWR(row, byteoff) (((row) * 128 + (byteoff)) ^ (((row) & 7) << 4))

// ---------------------------------------------------------------------------
// Fused prepass: len + input cvt + both weight transposes, one launch.
// ---------------------------------------------------------------------------
#define PREP_CVT0   4
#define PREP_CVTN   2048
#define PREP_TQ0    (PREP_CVT0 + PREP_CVTN)          // 2052
#define PREP_TQN    ((H3 / 32) * (HH / 32))          // 3072
#define PREP_TO0    (PREP_TQ0 + PREP_TQN)            // 5124
#define PREP_TON    ((HH / 32) * (HH / 32))          // 1024
#define PREP_BLOCKS (PREP_TO0 + PREP_TON)            // 6148

__global__ void prep_kernel(
    const unsigned char* __restrict__ mask, const float* __restrict__ inp,
    const float* __restrict__ w_qkv, const float* __restrict__ w_out,
    __half* __restrict__ xr, __half* __restrict__ wqT, __half* __restrict__ woT)
{
    __shared__ float sf[32][33];
    const int bid = blockIdx.x;
    const int tid = threadIdx.x;

    if (bid < 4) {
        __shared__ int sred[256];
        const unsigned int w0 = *(const unsigned int*)mask;
        const int b = bid;
        int cnt = 0;
        if (w0 == 0x01010101u) {
            for (int t = tid; t < TT; t += 256)
                cnt += (mask[(size_t)b * TT + t] != 0) ? 1 : 0;
        } else if (w0 == 0x3F800000u) {
            const float* m = (const float*)mask;
            for (int t = tid; t < TT; t += 256)
                cnt += (m[(size_t)b * TT + t] != 0.f) ? 1 : 0;
        } else {
            const int* m = (const int*)mask;
            for (int t = tid; t < TT; t += 256)
                cnt += (m[(size_t)b * TT + t] != 0) ? 1 : 0;
        }
        sred[tid] = cnt;
        __syncthreads();
        for (int s = 128; s > 0; s >>= 1) {
            if (tid < s) sred[tid] += sred[tid + s];
            __syncthreads();
        }
        if (tid == 0) g_len[b] = sred[0];
    } else if (bid < PREP_TQ0) {
        const float4* in = (const float4*)inp;
        uint2* out = (uint2*)xr;
        const int n4 = (BB * TT * HH) / 4;
        for (int i = (bid - PREP_CVT0) * 256 + tid; i < n4;
             i += PREP_CVTN * 256) {
            float4 v = in[i];
            out[i] = make_uint2(packh2(v.x, v.y), packh2(v.z, v.w));
        }
    } else {
        const float* S;
        __half* D;
        int R, C, tb;
        if (bid < PREP_TO0) {
            S = w_qkv; D = wqT; R = HH; C = H3; tb = bid - PREP_TQ0;
        } else {
            S = w_out; D = woT; R = HH; C = HH; tb = bid - PREP_TO0;
        }
        const int nbx = C / 32;
        const int bx = tb % nbx;
        const int by = tb / nbx;
        const int tx = tid & 31;
        const int ty = tid >> 5;
        const int x = bx * 32 + tx;
        const int y0 = by * 32;
        #pragma unroll
        for (int i = ty; i < 32; i += 8)
            sf[i][tx] = S[(size_t)(y0 + i) * C + x];
        __syncthreads();
        const int xo = y0 + tx;
        const int yo0 = bx * 32;
        #pragma unroll
        for (int i = ty; i < 32; i += 8)
            D[(size_t)(yo0 + i) * R + xo] = __float2half_rn(sf[tx][i]);
    }
}

// ---------------------------------------------------------------------------
// fp16 HMMA GEMM (R14/R15-proven): 3-stage cp.async.cg, ONE sync per chunk.
// CTA 128x128, K-chunk 64 halves, 8 warps (2x4), warp tile 64x32, m16n8k16.
// LENSKIP: early-exit CTAs computing K/V rows for padded tokens.
// ---------------------------------------------------------------------------
#define TG_AST  16384
#define TG_SMEM (6 * TG_AST)

template <bool HOUT, bool LENSKIP>
__global__ __launch_bounds__(256) void hgemm(
    const __half* __restrict__ A, const __half* __restrict__ Bt,
    const float* __restrict__ bias, void* __restrict__ Cv,
    int M, int N, int K)
{
    extern __shared__ char smem[];
    const uint32_t base = smem_u32(smem);

    const int brow  = blockIdx.y * 128;
    const int bcol  = blockIdx.x * 128;

    if (LENSKIP) {
        const int b  = brow >> 11;
        const int t0 = brow & 2047;
        const int lb = (g_len[b] + 63) & ~63;
        if (bcol >= HH && t0 >= lb) return;
    }

    const int tid   = threadIdx.x;
    const int warp  = tid >> 5;
    const int lane  = tid & 31;
    const int g     = lane >> 2;
    const int t     = lane & 3;
    const int warpM = warp & 1;
    const int warpN = warp >> 1;

    uint32_t sA[3], sB[3];
    #pragma unroll
    for (int s = 0; s < 3; s++) {
        sA[s] = base + s * TG_AST;
        sB[s] = base + 3 * TG_AST + s * TG_AST;
    }

    const int lrow = tid >> 1;
    const int lg   = (tid & 1) * 4;
    const __half* Ap = A  + (size_t)(brow + lrow) * K + lg * 8;
    const __half* Bp = Bt + (size_t)(bcol + lrow) * K + lg * 8;
    uint32_t swl[4];
    #pragma unroll
    for (int q = 0; q < 4; q++) swl[q] = SWR(lrow, (lg + q) * 16);

    const int arow16 = lane & 15;
    const int acol16 = (lane >> 4) * 16;
    const int brow_i = (lane & 7) + (lane >> 4) * 8;
    const int bcol_i = ((lane >> 3) & 1) * 16;

    float acc[4][4][4];
    #pragma unroll
    for (int i = 0; i < 4; i++)
        #pragma unroll
        for (int j = 0; j < 4; j++)
            #pragma unroll
            for (int q = 0; q < 4; q++) acc[i][j][q] = 0.f;

    const int nch = K >> 6;

    #pragma unroll
    for (int pc = 0; pc < 2; pc++) {
        #pragma unroll
        for (int q = 0; q < 4; q++) {
            CP16(sA[pc] + swl[q], Ap + pc * 64 + q * 8);
            CP16(sB[pc] + swl[q], Bp + pc * 64 + q * 8);
        }
        CPCOMMIT();
    }

    int st = 0, sp = 2;
    for (int kc = 0; kc < nch; kc++) {
        if (kc < nch - 1)
            asm volatile("cp.async.wait_group 1;" ::: "memory");
        else
            asm volatile("cp.async.wait_group 0;" ::: "memory");
        __syncthreads();

        if (kc + 2 < nch) {
            const __half* Ap2 = Ap + (kc + 2) * 64;
            const __half* Bp2 = Bp + (kc + 2) * 64;
            #pragma unroll
            for (int q = 0; q < 4; q++) {
                CP16(sA[sp] + swl[q], Ap2 + q * 8);
                CP16(sB[sp] + swl[q], Bp2 + q * 8);
            }
            CPCOMMIT();
        }

        const uint32_t aBase = sA[st];
        const uint32_t bBase = sB[st];

        #pragma unroll
        for (int ks = 0; ks < 4; ks++) {
            const int kb = ks * 32;
            unsigned af[4][4];
            #pragma unroll
            for (int mt = 0; mt < 4; mt++) {
                const int r = warpM * 64 + mt * 16 + arow16;
                LDSM4(af[mt][0], af[mt][1], af[mt][2], af[mt][3],
                      aBase + SWR(r, kb + acol16));
            }
            unsigned bf[4][2];
            #pragma unroll
            for (int np = 0; np < 2; np++) {
                const int r = warpN * 32 + np * 16 + brow_i;
                unsigned r0, r1, r2, r3;
                LDSM4(r0, r1, r2, r3, bBase + SWR(r, kb + bcol_i));
                bf[np * 2][0] = r0;      bf[np * 2][1] = r1;
                bf[np * 2 + 1][0] = r2;  bf[np * 2 + 1][1] = r3;
            }
            #pragma unroll
            for (int mt = 0; mt < 4; mt++)
                #pragma unroll
                for (int nt = 0; nt < 4; nt++)
                    mma_f16(acc[mt][nt], af[mt], bf[nt]);
        }

        st = (st == 2) ? 0 : st + 1;
        sp = (sp == 2) ? 0 : sp + 1;
    }

    #pragma unroll
    for (int mt = 0; mt < 4; mt++) {
        const int r0 = brow + warpM * 64 + mt * 16 + g;
        #pragma unroll
        for (int nt = 0; nt < 4; nt++) {
            const int c = bcol + warpN * 32 + nt * 8 + 2 * t;
            const float bv0 = bias[c], bv1 = bias[c + 1];
            if (HOUT) {
                __half* C = (__half*)Cv;
                *(unsigned*)&C[(size_t)r0 * N + c] =
                    packh2(acc[mt][nt][0] + bv0, acc[mt][nt][1] + bv1);
                *(unsigned*)&C[(size_t)(r0 + 8) * N + c] =
                    packh2(acc[mt][nt][2] + bv0, acc[mt][nt][3] + bv1);
            } else {
                float* C = (float*)Cv;
                float2 v0 = {acc[mt][nt][0] + bv0, acc[mt][nt][1] + bv1};
                float2 v1 = {acc[mt][nt][2] + bv0, acc[mt][nt][3] + bv1};
                *(float2*)&C[(size_t)r0 * N + c]       = v0;
                *(float2*)&C[(size_t)(r0 + 8) * N + c] = v1;
            }
        }
    }
}

// ---------------------------------------------------------------------------
// FA2 fp16 attention: qt reversed (heavy diagonal CTAs first — LPT),
// K/V staged via cp.async.cg double-buffer (no register staging / STS burst).
// ---------------------------------------------------------------------------
#define AT_SMEM 49152

__global__ __launch_bounds__(256) void attn_h(
    const __half* __restrict__ qkv, __half* __restrict__ att)
{
    extern __shared__ char sm[];
    const uint32_t smb = smem_u32(sm);

    const int tid  = threadIdx.x;
    const int warp = tid >> 5;
    const int lane = tid & 31;
    const int g = lane >> 2;
    const int t = lane & 3;
    const int qt = (int)gridDim.x - 1 - (int)blockIdx.x;  // heavy tiles first
    const int b  = blockIdx.y >> 4;
    const int h  = blockIdx.y & 15;
    const int len = g_len[b];

    const __half* qb = qkv + (size_t)b * TT * H3 + h * HD;
    const __half* kb = qb + HH;
    const __half* vb = qb + 2 * HH;

    // ---- stage Q (128 rows x 64 halves = 128B rows) ----
    {
        const int r = tid >> 1;
        #pragma unroll
        for (int q = 0; q < 4; q++) {
            const int gq = (tid & 1) * 4 + q;
            uint4 v = *(const uint4*)(qb + (size_t)(qt * 128 + r) * H3 + gq * 8);
            *(uint4*)(sm + SWR(r, gq * 16)) = v;
        }
    }
    __syncthreads();

    const int arow16 = lane & 15;
    const int acol16 = (lane >> 4) * 16;
    const int brow_i = (lane & 7) + (lane >> 4) * 8;
    const int bcol_i = ((lane >> 3) & 1) * 16;

    unsigned qf[4][4];
    #pragma unroll
    for (int ks = 0; ks < 4; ks++)
        LDSM4(qf[ks][0], qf[ks][1], qf[ks][2], qf[ks][3],
              smb + SWR(warp * 16 + arow16, ks * 32 + acol16));
    __syncthreads();   // Q staging region now reusable (K buffers)

    float m0 = -1e30f, m1 = -1e30f, l0 = 0.f, l1 = 0.f;
    float o[8][4];
    #pragma unroll
    for (int nt = 0; nt < 8; nt++)
        #pragma unroll
        for (int q = 0; q < 4; q++) o[nt][q] = 0.f;

    const int row0 = qt * 128 + warp * 16 + g;
    const int kt_max = min(2 * qt + 1, (len - 1) >> 6);

    // K/V loader: row tid/4 (0..63), granules (tid&3)*2 + {0,1}
    const int rv  = tid >> 2;
    const int gk0 = (tid & 3) * 2;
    uint32_t kdst[2][2], vdst[2][2];
    #pragma unroll
    for (int bu = 0; bu < 2; bu++)
        #pragma unroll
        for (int j = 0; j < 2; j++) {
            const uint32_t sw = SWR(rv, (gk0 + j) * 16);
            kdst[bu][j] = smb + bu * 8192 + sw;
            vdst[bu][j] = smb + 16384 + bu * 8192 + sw;
        }

    // prologue: tile 0 -> buf 0
    #pragma unroll
    for (int j = 0; j < 2; j++) {
        const size_t ro = (size_t)rv * H3 + (gk0 + j) * 8;
        CP16(kdst[0][j], kb + ro);
        CP16(vdst[0][j], vb + ro);
    }
    CPCOMMIT();

    for (int kt = 0; kt <= kt_max; kt++) {
        const int buf = kt & 1;
        const uint32_t kbuf = smb + buf * 8192;
        const uint32_t vbuf = smb + 16384 + buf * 8192;

        asm volatile("cp.async.wait_group 0;" ::: "memory");
        __syncthreads();   // tile kt visible to all warps; buf^1 reads done

        if (kt < kt_max) {
            #pragma unroll
            for (int j = 0; j < 2; j++) {
                const size_t ro = (size_t)((kt + 1) * 64 + rv) * H3 + (gk0 + j) * 8;
                CP16(kdst[buf ^ 1][j], kb + ro);
                CP16(vdst[buf ^ 1][j], vb + ro);
            }
            CPCOMMIT();
        }

        // ---- S = Q @ K^T ----
        float s[8][4];
        #pragma unroll
        for (int nt = 0; nt < 8; nt++)
            #pragma unroll
            for (int q = 0; q < 4; q++) s[nt][q] = 0.f;

        #pragma unroll
        for (int ks = 0; ks < 4; ks++) {
            unsigned bf[8][2];
            #pragma unroll
            for (int np = 0; np < 4; np++) {
                unsigned r0, r1, r2, r3;
                LDSM4(r0, r1, r2, r3,
                      kbuf + SWR(np * 16 + brow_i, ks * 32 + bcol_i));
                bf[np * 2][0] = r0;      bf[np * 2][1] = r1;
                bf[np * 2 + 1][0] = r2;  bf[np * 2 + 1][1] = r3;
            }
            #pragma unroll
            for (int nt = 0; nt < 8; nt++)
                mma_f16(s[nt], qf[ks], bf[nt]);
        }

        // ---- scale + mask ----
        #pragma unroll
        for (int nt = 0; nt < 8; nt++) {
            const int c0 = kt * 64 + nt * 8 + 2 * t;
            s[nt][0] = (c0     <= row0     && c0     < len) ? s[nt][0] * 0.125f : -1e30f;
            s[nt][1] = (c0 + 1 <= row0     && c0 + 1 < len) ? s[nt][1] * 0.125f : -1e30f;
            s[nt][2] = (c0     <= row0 + 8 && c0     < len) ? s[nt][2] * 0.125f : -1e30f;
            s[nt][3] = (c0 + 1 <= row0 + 8 && c0 + 1 < len) ? s[nt][3] * 0.125f : -1e30f;
        }

        // ---- register online softmax ----
        float mx0 = -1e30f, mx1 = -1e30f;
        #pragma unroll
        for (int nt = 0; nt < 8; nt++) {
            mx0 = fmaxf(mx0, fmaxf(s[nt][0], s[nt][1]));
            mx1 = fmaxf(mx1, fmaxf(s[nt][2], s[nt][3]));
        }
        mx0 = fmaxf(mx0, __shfl_xor_sync(0xffffffffu, mx0, 1));
        mx0 = fmaxf(mx0, __shfl_xor_sync(0xffffffffu, mx0, 2));
        mx1 = fmaxf(mx1, __shfl_xor_sync(0xffffffffu, mx1, 1));
        mx1 = fmaxf(mx1, __shfl_xor_sync(0xffffffffu, mx1, 2));

        const float mn0 = fmaxf(m0, mx0);
        const float mn1 = fmaxf(m1, mx1);
        const float a0 = __expf(m0 - mn0);
        const float a1 = __expf(m1 - mn1);
        m0 = mn0; m1 = mn1;

        float sum0 = 0.f, sum1 = 0.f;
        #pragma unroll
        for (int nt = 0; nt < 8; nt++) {
            s[nt][0] = __expf(s[nt][0] - mn0);
            s[nt][1] = __expf(s[nt][1] - mn0);
            s[nt][2] = __expf(s[nt][2] - mn1);
            s[nt][3] = __expf(s[nt][3] - mn1);
            sum0 += s[nt][0] + s[nt][1];
            sum1 += s[nt][2] + s[nt][3];
        }
        sum0 += __shfl_xor_sync(0xffffffffu, sum0, 1);
        sum0 += __shfl_xor_sync(0xffffffffu, sum0, 2);
        sum1 += __shfl_xor_sync(0xffffffffu, sum1, 1);
        sum1 += __shfl_xor_sync(0xffffffffu, sum1, 2);
        l0 = l0 * a0 + sum0;
        l1 = l1 * a1 + sum1;

        #pragma unroll
        for (int nt = 0; nt < 8; nt++) {
            o[nt][0] *= a0; o[nt][1] *= a0;
            o[nt][2] *= a1; o[nt][3] *= a1;
        }

        // ---- P -> warp-private smem ----
        const int pOff = 32768 + warp * 2048;
        #pragma unroll
        for (int nt = 0; nt < 8; nt++) {
            *(unsigned*)(sm + pOff + SWR(g,     nt * 16 + 4 * t)) =
                packh2(s[nt][0], s[nt][1]);
            *(unsigned*)(sm + pOff + SWR(g + 8, nt * 16 + 4 * t)) =
                packh2(s[nt][2], s[nt][3]);
        }
        __syncwarp();

        // ---- O += P @ V ----
        const uint32_t pB = smb + pOff;
        #pragma unroll
        for (int ks = 0; ks < 4; ks++) {
            unsigned pf[4];
            LDSM4(pf[0], pf[1], pf[2], pf[3],
                  pB + SWR(arow16, ks * 32 + acol16));
            unsigned vf[8][2];
            #pragma unroll
            for (int np = 0; np < 4; np++) {
                unsigned r0, r1, r2, r3;
                LDSM4T(r0, r1, r2, r3,
                       vbuf + SWR(ks * 16 + ((lane >> 3) & 1) * 8 + (lane & 7),
                                  np * 32 + (lane >> 4) * 16));
                vf[np * 2][0] = r0;      vf[np * 2][1] = r1;
                vf[np * 2 + 1][0] = r2;  vf[np * 2 + 1][1] = r3;
            }
            #pragma unroll
            for (int nt = 0; nt < 8; nt++)
                mma_f16(o[nt], pf, vf[nt]);
        }
    }

    // ---- epilogue ----
    {
        const float inv0 = 1.f / l0;
        const float inv1 = 1.f / l1;
        __half* ob = att + (size_t)b * TT * HH
                   + (size_t)(qt * 128 + warp * 16) * HH + h * HD;
        #pragma unroll
        for (int nt = 0; nt < 8; nt++) {
            const int c = nt * 8 + 2 * t;
            *(unsigned*)&ob[(size_t)g * HH + c] =
                packh2(o[nt][0] * inv0, o[nt][1] * inv0);
            *(unsigned*)&ob[(size_t)(g + 8) * HH + c] =
                packh2(o[nt][2] * inv1, o[nt][3] * inv1);
        }
    }
}

// ---------------------------------------------------------------------------

extern "C" void kernel_launch(void* const* d_in, const int* in_sizes, int n_in,
                              void* d_out, int out_size)
{
    const float*         inp   = (const float*)d_in[0];
    const unsigned char* mask  = (const unsigned char*)d_in[1];
    const float*         w_qkv = (const float*)d_in[2];
    const float*         b_qkv = (const float*)d_in[3];
    const float*         w_out = (const float*)d_in[4];
    const float*         b_out = (const float*)d_in[5];
    float*               out   = (float*)d_out;

    __half *qkv_p, *att_p, *xr_p, *wqT_p, *woT_p;
    cudaGetSymbolAddress((void**)&qkv_p, g_qkv);
    cudaGetSymbolAddress((void**)&att_p, g_att);
    cudaGetSymbolAddress((void**)&xr_p,  g_xr);
    cudaGetSymbolAddress((void**)&wqT_p, g_wqT);
    cudaGetSymbolAddress((void**)&woT_p, g_woT);

    cudaFuncSetAttribute(attn_h,
                         cudaFuncAttributeMaxDynamicSharedMemorySize, AT_SMEM);
    cudaFuncSetAttribute((hgemm<true, true>),
                         cudaFuncAttributeMaxDynamicSharedMemorySize, TG_SMEM);
    cudaFuncSetAttribute((hgemm<false, false>),
                         cudaFuncAttributeMaxDynamicSharedMemorySize, TG_SMEM);

    prep_kernel<<<PREP_BLOCKS, 256>>>(mask, inp, w_qkv, w_out,
                                      xr_p, wqT_p, woT_p);

    hgemm<true, true><<<dim3(H3 / 128, (BB * TT) / 128), 256, TG_SMEM>>>(
        xr_p, wqT_p, b_qkv, qkv_p, BB * TT, H3, HH);
    attn_h<<<dim3(TT / 128, BB * NH), 256, AT_SMEM>>>(qkv_p, att_p);
    hgemm<false, false><<<dim3(HH / 128, (BB * TT) / 128), 256, TG_SMEM>>>(
        att_p, woT_p, b_out, out, BB * TT, HH, HH);
}